// round 10
// baseline (speedup 1.0000x reference)
#include <cuda_runtime.h>

#define NB 2
#define NC 64
#define D  64
#define NVOX (D*D*D)            // 262144
#define NCH  (NB*NC)            // 128
#define TOT  (NCH*NVOX)         // 33554432

#define FIX_T   0.02f
#define MAXFIX  (1<<22)

#define PSTR 65                 // padded smem row stride (float2 elems)
#define ZPB  8                  // z-planes per box_wh block

#define TL 4                    // l-tile per thread
#define TV 4                    // voxel-tile per thread
#define VBLK 64                 // voxels per proj block

// Scratch (no cudaMalloc allowed)
__device__ float2 g_p [TOT];    // (qk, qkv) bit-exact proj output (fixup source)
__device__ float2 g_t2[TOT];    // after w+h passes
__device__ float2 g_wqk_t[NC*NC];  // weights transposed [c][l]: (wq, wk)
__device__ float2 g_wv2_t[NC*NC];  // [c][l]: (wv, wv)
__device__ int    g_cnt;
__device__ int    g_fixlist[MAXFIX];

__global__ void reset_kernel() { g_cnt = 0; }
__global__ void noop_kernel() {}

// One-time weight transpose+pack: [l][c] row-major -> [c][l] packed forms.
__global__ __launch_bounds__(256) void wtrans_kernel(
    const float* __restrict__ qw, const float* __restrict__ kw,
    const float* __restrict__ vw)
{
    const int i = blockIdx.x * 256 + threadIdx.x;   // 0..4095, i = l*64+c
    const int l = i >> 6, c = i & 63;
    const float q = qw[i], k = kw[i], v = vw[i];
    g_wqk_t[c*NC + l] = make_float2(q, k);
    g_wv2_t[c*NC + l] = make_float2(v, v);
}

// ---------------------------------------------------------------------------
// Stage 1: register-tiled projection GEMM. Thread computes TL=4 l's x TV=4
// voxels. Accumulation per (l,voxel): single packed fma.rn.f32x2 chain over
// ascending c (each lane IEEE fp32) -> bit-identical to the validated scalar
// sequential chains. av packs 2 voxels per FMA2 with duplicated wv weights.
// qk = q*k; qkv = qk*v single roundings. g_p bit-exactness is load-bearing
// for near-zero denominators (fixup).
// ---------------------------------------------------------------------------
__global__ __launch_bounds__(256) void proj_kernel(
    const float* __restrict__ mov, const float* __restrict__ fix)
{
    extern __shared__ float psmem[];
    float2* sWQK = (float2*)psmem;              // [c][l] (wq,wk)   32 KB
    float2* sWV2 = sWQK + NC*NC;                // [c][l] (wv,wv)   32 KB
    float2* sMF  = sWV2 + NC*NC;                // [c][vox] (m,f)   32 KB
    float*  sFv  = (float*)(sMF + NC*NC);       // [c][vox] f       16 KB

    const int tid = threadIdx.x;

    for (int i = tid; i < NC*NC; i += 256) {
        sWQK[i] = g_wqk_t[i];
        sWV2[i] = g_wv2_t[i];
    }

    const int gid0 = blockIdx.x * VBLK;
    const int b    = (gid0 >= NVOX) ? 1 : 0;
    const int n0   = gid0 - b * NVOX;
    const float* mp = mov + (long)b*NC*NVOX + n0;
    const float* fp = fix + (long)b*NC*NVOX + n0;

    for (int i = tid; i < NC*VBLK; i += 256) {    // i = c*64 + vox
        const int c = i >> 6, vox = i & 63;
        const float m = mp[(long)c*NVOX + vox];
        const float f = fp[(long)c*NVOX + vox];
        sMF[i] = make_float2(m, f);
        sFv[i] = f;
    }
    __syncthreads();

    const int l0 = (tid >> 4) * TL;     // 16 l-teams
    const int v0 = (tid & 15) * TV;     // 16 vox-teams

    unsigned long long aqk[TL][TV];     // lanes (aq, ak)
    unsigned long long av [TL][TV/2];   // lanes (av_voxEven, av_voxOdd)
    #pragma unroll
    for (int li = 0; li < TL; li++) {
        #pragma unroll
        for (int vi = 0; vi < TV; vi++) aqk[li][vi] = 0ull;
        #pragma unroll
        for (int p = 0; p < TV/2; p++)  av[li][p] = 0ull;
    }

    #pragma unroll 4
    for (int c = 0; c < NC; c++) {
        const ulonglong2* wp = (const ulonglong2*)(sWQK + c*NC + l0);
        const ulonglong2 w01 = wp[0], w23 = wp[1];
        const ulonglong2* vp = (const ulonglong2*)(sWV2 + c*NC + l0);
        const ulonglong2 v01 = vp[0], v23 = vp[1];
        const ulonglong2* mq = (const ulonglong2*)(sMF + c*NC + v0);
        const ulonglong2 m01 = mq[0], m23 = mq[1];
        const ulonglong2 fq  = *(const ulonglong2*)(sFv + c*NC + v0);

        const unsigned long long wl[TL] = {w01.x, w01.y, w23.x, w23.y};
        const unsigned long long vl[TL] = {v01.x, v01.y, v23.x, v23.y};
        const unsigned long long mv[TV] = {m01.x, m01.y, m23.x, m23.y};
        const unsigned long long fv[TV/2] = {fq.x, fq.y};

        #pragma unroll
        for (int li = 0; li < TL; li++) {
            #pragma unroll
            for (int vi = 0; vi < TV; vi++)
                asm("fma.rn.f32x2 %0, %1, %2, %0;"
                    : "+l"(aqk[li][vi]) : "l"(wl[li]), "l"(mv[vi]));
            #pragma unroll
            for (int p = 0; p < TV/2; p++)
                asm("fma.rn.f32x2 %0, %1, %2, %0;"
                    : "+l"(av[li][p]) : "l"(vl[li]), "l"(fv[p]));
        }
    }

    const long ob = (long)b*NC*NVOX + n0 + v0;
    #pragma unroll
    for (int li = 0; li < TL; li++) {
        float r[2*TV];
        #pragma unroll
        for (int vi = 0; vi < TV; vi++) {
            float aq, ak, a0, a1;
            asm("mov.b64 {%0,%1}, %2;" : "=f"(aq), "=f"(ak) : "l"(aqk[li][vi]));
            asm("mov.b64 {%0,%1}, %2;" : "=f"(a0), "=f"(a1) : "l"(av[li][vi>>1]));
            const float avv = (vi & 1) ? a1 : a0;
            const float qk  = __fmul_rn(aq, ak);
            const float qkv = __fmul_rn(qk, avv);
            r[2*vi]   = qk;
            r[2*vi+1] = qkv;
        }
        float4* dst = (float4*)(g_p + ob + (long)(l0+li)*NVOX);
        dst[0] = make_float4(r[0], r[1], r[2], r[3]);
        dst[1] = make_float4(r[4], r[5], r[6], r[7]);
    }
}

// ---------------------------------------------------------------------------
// Stage 2ab (fused, software-pipelined): W then H box sums (R9, measured 112us).
// ---------------------------------------------------------------------------
__global__ __launch_bounds__(256) void box_wh_kernel()
{
    extern __shared__ float2 smp[];
    float2* P = smp;               // [64][PSTR] current input plane
    float2* Q = smp + D*PSTR;      // [64][PSTR] after w-pass

    const int tid  = threadIdx.x;
    const int z0   = blockIdx.x * ZPB;
    const int chan = blockIdx.y;
    const long cb  = (long)chan*NVOX;

    for (int i = tid; i < D*D; i += 256)
        P[(i >> 6)*PSTR + (i & 63)] = g_p[cb + (long)z0*(D*D) + i];
    __syncthreads();

    #pragma unroll 1
    for (int p = 0; p < ZPB; p++) {
        const long nb = cb + (long)(z0 + p + 1)*(D*D);
        const bool pf = (p + 1 < ZPB);
        float2 rA[8], rB[8];

        if (pf) {
            #pragma unroll
            for (int k = 0; k < 8; k++) rA[k] = g_p[nb + k*256 + tid];
        }

        // w-pass: P -> Q
        {
            const int h   = tid & 63;
            const int w0  = (tid >> 6) * 16;
            const float2* row = P + h*PSTR;
            float2* qrow = Q + h*PSTR;
            float sx = 0.f, sy = 0.f;
            const int j0 = (w0 >= 4) ? (w0 - 4) : 0;
            for (int j = j0; j < w0 + 4; j++) { sx += row[j].x; sy += row[j].y; }
            #pragma unroll
            for (int i = 0; i < 16; i++) {
                const int w = w0 + i;
                if (w + 4 < D) { sx += row[w+4].x; sy += row[w+4].y; }
                qrow[w] = make_float2(sx, sy);
                if (w >= 4) { sx -= row[w-4].x; sy -= row[w-4].y; }
            }
        }
        __syncthreads();

        if (pf) {
            #pragma unroll
            for (int k = 0; k < 8; k++) rB[k] = g_p[nb + (k+8)*256 + tid];
        }

        // h-pass: Q -> g_t2
        {
            const int w   = tid & 63;
            const int h0  = (tid >> 6) * 16;
            const long pbase = cb + (long)(z0 + p)*(D*D);
            float sx = 0.f, sy = 0.f;
            const int j0 = (h0 >= 4) ? (h0 - 4) : 0;
            for (int j = j0; j < h0 + 4; j++) {
                const float2 v = Q[j*PSTR + w];
                sx += v.x; sy += v.y;
            }
            #pragma unroll
            for (int i = 0; i < 16; i++) {
                const int h = h0 + i;
                if (h + 4 < D) {
                    const float2 v = Q[(h+4)*PSTR + w];
                    sx += v.x; sy += v.y;
                }
                g_t2[pbase + h*D + w] = make_float2(sx, sy);
                if (h >= 4) {
                    const float2 v = Q[(h-4)*PSTR + w];
                    sx -= v.x; sy -= v.y;
                }
            }
        }

        if (pf) {
            #pragma unroll
            for (int k = 0; k < 8; k++) {
                const int i = k*256 + tid;
                P[(i >> 6)*PSTR + (i & 63)] = rA[k];
            }
            #pragma unroll
            for (int k = 0; k < 8; k++) {
                const int i = (k+8)*256 + tid;
                P[(i >> 6)*PSTR + (i & 63)] = rB[k];
            }
        }
        __syncthreads();
    }
}

// ---------------------------------------------------------------------------
// Stage 2c: box sum along Z + division; flag near-zero denominators.
// ---------------------------------------------------------------------------
__global__ __launch_bounds__(256) void box_z_div_kernel(float* __restrict__ out)
{
    const int t    = threadIdx.x;
    const int wp   = t & 31;
    const int h    = blockIdx.x * 8 + (t >> 5);
    const int chan = blockIdx.y;
    const long ebase = (long)chan*NVOX + (long)h*D + 2*wp;
    const long base  = ebase >> 1;
    const float4* src = (const float4*)g_t2;
    float2*       o2  = (float2*)out;

    float4 ring[9];
    float4 s = make_float4(0.f, 0.f, 0.f, 0.f);
    #pragma unroll
    for (int j = 0; j < 4; j++) {
        float4 v = src[base + (long)j*(D*D/2)];
        ring[j % 9] = v;
        s.x += v.x; s.y += v.y; s.z += v.z; s.w += v.w;
    }
    #pragma unroll
    for (int i = 0; i < D; i++) {
        const int j = i + 4;
        if (j < D) {
            float4 v = src[base + (long)j*(D*D/2)];
            ring[j % 9] = v;
            s.x += v.x; s.y += v.y; s.z += v.z; s.w += v.w;
        }
        const long eidx = ebase + (long)i*(D*D);
        o2[eidx >> 1] = make_float2(__fdiv_rn(s.y, s.x), __fdiv_rn(s.w, s.z));
        if (fabsf(s.x) < FIX_T) {
            int slot = atomicAdd(&g_cnt, 1);
            if (slot < MAXFIX) g_fixlist[slot] = (int)eidx;
        }
        if (fabsf(s.z) < FIX_T) {
            int slot = atomicAdd(&g_cnt, 1);
            if (slot < MAXFIX) g_fixlist[slot] = (int)(eidx + 1);
        }
        const int j2 = i - 4;
        if (j2 >= 0) {
            float4 v = ring[j2 % 9];
            s.x -= v.x; s.y -= v.y; s.z -= v.z; s.w -= v.w;
        }
    }
}

// ---------------------------------------------------------------------------
// Stage 3: exact fixup — reference's sequential in-bounds 729-tap fold
// (ascending z,h,w; fp32 adds; init 0) over the bit-exact g_p field.
// ---------------------------------------------------------------------------
__global__ __launch_bounds__(256) void fixup_kernel(float* __restrict__ out)
{
    int cnt = g_cnt; if (cnt > MAXFIX) cnt = MAXFIX;
    for (int idx = blockIdx.x*256 + threadIdx.x; idx < cnt; idx += gridDim.x*256) {
        const int v    = g_fixlist[idx];
        const int chan = v >> 18;
        const int rem  = v & (NVOX-1);
        const int z = rem >> 12;
        const int h = (rem >> 6) & 63;
        const int w = rem & 63;
        const long cb = (long)chan*NVOX;

        const int zlo = z-4 < 0 ? 0 : z-4, zhi = z+4 > 63 ? 63 : z+4;
        const int hlo = h-4 < 0 ? 0 : h-4, hhi = h+4 > 63 ? 63 : h+4;
        const int wlo = w-4 < 0 ? 0 : w-4, whi = w+4 > 63 ? 63 : w+4;

        float sD = 0.f, sN = 0.f;
        for (int dz = zlo; dz <= zhi; dz++)
            for (int dh = hlo; dh <= hhi; dh++) {
                const float2* row = g_p + cb + ((long)dz*D + dh)*D;
                for (int dw = wlo; dw <= whi; dw++) {
                    float2 x = row[dw];
                    sD = __fadd_rn(sD, x.x);
                    sN = __fadd_rn(sN, x.y);
                }
            }
        out[v] = __fdiv_rn(sN, sD);
    }
}

extern "C" void kernel_launch(void* const* d_in, const int* in_sizes, int n_in,
                              void* d_out, int out_size) {
    (void)in_sizes; (void)n_in; (void)out_size;
    const float* mov = (const float*)d_in[0];
    const float* fix = (const float*)d_in[1];
    const float* qw  = (const float*)d_in[2];
    const float* kw  = (const float*)d_in[3];
    const float* vw  = (const float*)d_in[4];
    float* out = (float*)d_out;

    const int proj_smem = (3*NC*NC)*sizeof(float2) + NC*NC*sizeof(float); // 114688
    const int wh_smem   = 2*D*PSTR * sizeof(float2);                      // 66560
    cudaFuncSetAttribute(proj_kernel,
                         cudaFuncAttributeMaxDynamicSharedMemorySize, proj_smem);
    cudaFuncSetAttribute(box_wh_kernel,
                         cudaFuncAttributeMaxDynamicSharedMemorySize, wh_smem);

    reset_kernel<<<1, 1>>>();
    wtrans_kernel<<<16, 256>>>(qw, kw, vw);
    noop_kernel<<<1, 32>>>();
    proj_kernel<<<(NB*NVOX)/VBLK, 256, proj_smem>>>(mov, fix);   // captured idx 3
    box_wh_kernel<<<dim3(D/ZPB, NCH), 256, wh_smem>>>();
    box_z_div_kernel<<<dim3(8, NCH), 256>>>(out);
    fixup_kernel<<<512, 256>>>(out);
}